// round 13
// baseline (speedup 1.0000x reference)
#include <cuda_runtime.h>
#include <cuda_bf16.h>
#include <cstdint>

#define N_ITEMS  262144
#define DIM      128
#define NCB      3
#define KCW      256
#define TM       128
#define NTILES   (N_ITEMS / TM)   // 2048
#define NTHREADS 512
#define GRID     148
#define STB      272              // B row stride bytes (136 bf16)
#define RSW      132              // raw row stride words (528 B)
#define CAPW     3072
#define MCOEF    0.040f

__device__ float g_cc[NCB * KCW];
__device__ int   g_cmax[NCB];
__device__ float g_res[(size_t)N_ITEMS * DIM];
__device__ int   g_idx[2 * N_ITEMS];

__device__ __forceinline__ uint32_t s2u(const void* p) {
    return (uint32_t)__cvta_generic_to_shared(p);
}
#define CPA16(saddr, gptr) asm volatile("cp.async.ca.shared.global [%0], [%1], 16;" :: "r"(saddr), "l"(gptr))
#define CPCOMMIT()         asm volatile("cp.async.commit_group;")
#define CPWAIT0()          asm volatile("cp.async.wait_group 0;" ::: "memory")
#define LDSM4(r0,r1,r2,r3,a) asm volatile("ldmatrix.sync.aligned.m8n8.x4.shared.b16 {%0,%1,%2,%3}, [%4];" : "=r"(r0),"=r"(r1),"=r"(r2),"=r"(r3) : "r"(a))
#define MMA16816(d,a0,a1,a2,a3,b0,b1) asm volatile( \
    "mma.sync.aligned.m16n8k16.row.col.f32.bf16.bf16.f32 " \
    "{%0,%1,%2,%3}, {%4,%5,%6,%7}, {%8,%9}, {%0,%1,%2,%3};" \
    : "+f"((d)[0]),"+f"((d)[1]),"+f"((d)[2]),"+f"((d)[3]) \
    : "r"(a0),"r"(a1),"r"(a2),"r"(a3),"r"(b0),"r"(b1))
#define CVTBF2(o, lo, hi) asm("cvt.rn.bf16x2.f32 %0, %1, %2;" : "=r"(o) : "f"(hi), "f"(lo))

__device__ __forceinline__ uint32_t ford(float f) {
    uint32_t u = __float_as_uint(f);
    return (u & 0x80000000u) ? ~u : (u | 0x80000000u);
}

__global__ void cc_kernel(const float* __restrict__ codebooks) {
    int row = blockIdx.x * 32 + threadIdx.x;
    if (row >= NCB * KCW) return;
    const float* r = codebooks + (size_t)row * DIM;
    double s = 0.0;
    #pragma unroll 8
    for (int k = 0; k < DIM; k++) { double v = (double)r[k]; s += v * v; }
    g_cc[row] = (float)s;
    float nrm = sqrtf((float)s) * 1.0001f;
    atomicMax(&g_cmax[row / KCW], __float_as_int(nrm));
}

// exact d2: sequential k-ascending fmaf chain (validated R3-R12); r may be smem
__device__ __noinline__ float exact_d2(const float* __restrict__ r,
                                       const float* __restrict__ c,
                                       float rr, float ccj) {
    float dot = 0.f;
    #pragma unroll
    for (int m = 0; m < 32; m++) {
        float4 a = ((const float4*)r)[m];
        float4 b = ((const float4*)c)[m];
        dot = __fmaf_rn(a.x, b.x, dot);
        dot = __fmaf_rn(a.y, b.y, dot);
        dot = __fmaf_rn(a.z, b.z, dot);
        dot = __fmaf_rn(a.w, b.w, dot);
    }
    return __fadd_rn(__fmaf_rn(-2.f, dot, rr), ccj);
}

// smem offsets
#define O_B     0            // 256*272 = 69632
#define O_R0    69632        // 128*528 = 67584
#define O_R1    137216       // 67584
#define O_CC    204800       // 1024
#define O_RRS   205824       // 512
#define O_HM    206336       // 1024
#define O_EKEY  207360       // 1024
#define O_WL    208384       // 12288
#define O_BEST  220672       // 512
#define O_WCNT  221184       // 16
#define SMEM_BYTES (221200 + 1024)

__global__ __launch_bounds__(NTHREADS, 1)
void rvq_kernel(const float* __restrict__ x,
                const float* __restrict__ codebooks,
                float* __restrict__ out, int mode)
{
    extern __shared__ char smraw[];
    char* smem = (char*)(((uintptr_t)smraw + 1023) & ~(uintptr_t)1023);
    float* rawb[2] = { (float*)(smem + O_R0), (float*)(smem + O_R1) };
    float* cc_s = (float*)(smem + O_CC);
    float* rrs  = (float*)(smem + O_RRS);
    float* hm   = (float*)(smem + O_HM);
    unsigned long long* ekey = (unsigned long long*)(smem + O_EKEY);
    uint32_t* wl = (uint32_t*)(smem + O_WL);
    int*   best = (int*)(smem + O_BEST);
    int*   wcnt = (int*)(smem + O_WCNT);

    const int t = threadIdx.x, w = t >> 5, lane = t & 31;
    const uint32_t sB = s2u(smem + O_B);
    const int mrow0 = 16 * (w & 7);
    const int colbase = 128 * (w >> 3);

    auto prefetch_tile = [&](const float* src, int tl, int buf) {
        const char* gb = (const char*)(src + (size_t)tl * (TM * DIM));
        uint32_t sb = s2u(rawb[buf]);
        #pragma unroll
        for (int n = 0; n < 8; n++) {
            int g = t + NTHREADS * n;        // 0..4095 granules of 16B
            CPA16(sb + (g >> 5) * (RSW * 4) + (g & 31) * 16, gb + g * 16);
        }
        CPCOMMIT();
    };

    for (int stage = 0; stage < NCB; stage++) {
        __syncthreads();
        const float cmax = __int_as_float(g_cmax[stage]);
        // ---- B conversion (hi bf16): 2 threads per codeword row ----
        {
            int row = t >> 1, h = t & 1;
            const float4* cr = (const float4*)(codebooks + ((size_t)stage * KCW + row) * DIM + h * 64);
            char* hrow = smem + O_B + row * STB + h * 128;
            #pragma unroll
            for (int m = 0; m < 8; m++) {
                float4 v0 = cr[2 * m], v1 = cr[2 * m + 1];
                uint4 o;
                CVTBF2(o.x, v0.x, v0.y); CVTBF2(o.y, v0.z, v0.w);
                CVTBF2(o.z, v1.x, v1.y); CVTBF2(o.w, v1.z, v1.w);
                *(uint4*)(hrow + m * 16) = o;
            }
            if (t < KCW) cc_s[t] = g_cc[stage * KCW + t];
        }
        const float* src = (stage == 0) ? x : g_res;
        __syncthreads();

        int tl0 = blockIdx.x;
        if (tl0 < NTILES) prefetch_tile(src, tl0, 0);

        int it = 0;
        for (int tl = tl0; tl < NTILES; tl += GRID, it++) {
            int buf = it & 1;
            float* raw = rawb[buf];

            CPWAIT0();
            __syncthreads();              // tile raw ready; prev tile fully done

            int tln = tl + GRID;
            if (tln < NTILES) prefetch_tile(src, tln, buf ^ 1);

            // ---- phase 1: rr from smem raw (R12-exact association) + init ----
            {
                int i = t >> 2, q = t & 3;
                const float4* rp = (const float4*)(raw + i * RSW + q * 32);
                double s = 0.0;
                #pragma unroll
                for (int m = 0; m < 8; m++) {
                    float4 v = rp[m];
                    double a = v.x, b = v.y, c = v.z, d = v.w;
                    s += a * a; s += b * b; s += c * c; s += d * d;
                }
                s += __shfl_xor_sync(0xffffffffu, s, 1);
                s += __shfl_xor_sync(0xffffffffu, s, 2);
                if (q == 0) rrs[i] = (float)s;
                if (t < TM) ekey[t] = ~0ull;
                if (t == 0) *wcnt = 0;
            }
            __syncthreads();

            // ---- phase 2: MMA; A frags direct from raw fp32 (LDS + cvt) ----
            float d[16][4];
            #pragma unroll
            for (int nt = 0; nt < 16; nt++)
                #pragma unroll
                for (int e = 0; e < 4; e++) d[nt][e] = 0.f;

            const float* ar0 = raw + (mrow0 + (lane >> 2)) * RSW + (lane & 3) * 2;
            const float* ar1 = ar0 + 8 * RSW;
            const uint32_t bAddr0 = sB + (colbase + ((lane >> 4) & 1) * 8 + (lane & 7)) * STB
                                       + ((lane >> 3) & 1) * 16;
            #pragma unroll 1
            for (int ks = 0; ks < 8; ks++) {
                int k0 = ks * 16;
                float2 f0 = *(const float2*)(ar0 + k0);
                float2 f1 = *(const float2*)(ar1 + k0);
                float2 f2 = *(const float2*)(ar0 + k0 + 8);
                float2 f3 = *(const float2*)(ar1 + k0 + 8);
                uint32_t a0, a1, a2, a3;
                CVTBF2(a0, f0.x, f0.y);
                CVTBF2(a1, f1.x, f1.y);
                CVTBF2(a2, f2.x, f2.y);
                CVTBF2(a3, f3.x, f3.y);
                #pragma unroll
                for (int ntp = 0; ntp < 8; ntp++) {
                    uint32_t b0, b1, b2, b3;
                    LDSM4(b0, b1, b2, b3, bAddr0 + ntp * 16 * STB + ks * 32);
                    MMA16816(d[2 * ntp],     a0, a1, a2, a3, b0, b1);
                    MMA16816(d[2 * ntp + 1], a0, a1, a2, a3, b2, b3);
                }
            }

            // ---- phase 3: approx d2 + per-item half-min ----
            const int item0 = mrow0 + (lane >> 2);
            const int item1 = item0 + 8;
            const float rr0 = rrs[item0], rr1 = rrs[item1];
            float mn0 = 3.0e38f, mn1 = 3.0e38f;
            #pragma unroll
            for (int nt = 0; nt < 16; nt++) {
                int n = colbase + nt * 8 + 2 * (lane & 3);
                float c0 = cc_s[n], c1 = cc_s[n + 1];
                d[nt][0] = __fadd_rn(__fmaf_rn(-2.f, d[nt][0], rr0), c0);
                d[nt][1] = __fadd_rn(__fmaf_rn(-2.f, d[nt][1], rr0), c1);
                d[nt][2] = __fadd_rn(__fmaf_rn(-2.f, d[nt][2], rr1), c0);
                d[nt][3] = __fadd_rn(__fmaf_rn(-2.f, d[nt][3], rr1), c1);
                mn0 = fminf(mn0, fminf(d[nt][0], d[nt][1]));
                mn1 = fminf(mn1, fminf(d[nt][2], d[nt][3]));
            }
            mn0 = fminf(mn0, __shfl_xor_sync(0xffffffffu, mn0, 1));
            mn0 = fminf(mn0, __shfl_xor_sync(0xffffffffu, mn0, 2));
            mn1 = fminf(mn1, __shfl_xor_sync(0xffffffffu, mn1, 1));
            mn1 = fminf(mn1, __shfl_xor_sync(0xffffffffu, mn1, 2));
            if ((lane & 3) == 0) {
                hm[(w >> 3) * TM + item0] = mn0;
                hm[(w >> 3) * TM + item1] = mn1;
            }
            __syncthreads();

            // ---- phase 4: candidate collection (provable 2M window) ----
            {
                float thr0 = fminf(hm[item0], hm[TM + item0]) + MCOEF * sqrtf(rr0) * cmax + 1e-3f;
                float thr1 = fminf(hm[item1], hm[TM + item1]) + MCOEF * sqrtf(rr1) * cmax + 1e-3f;
                #pragma unroll
                for (int nt = 0; nt < 16; nt++) {
                    int n = colbase + nt * 8 + 2 * (lane & 3);
                    #pragma unroll
                    for (int e = 0; e < 4; e++) {
                        int iti = (e < 2) ? item0 : item1;
                        float thr = (e < 2) ? thr0 : thr1;
                        if (d[nt][e] <= thr) {
                            int slot = atomicAdd(wcnt, 1);
                            if (slot < CAPW)
                                wl[slot] = ((uint32_t)iti << 16) | (uint32_t)(n + (e & 1));
                        }
                    }
                }
            }
            __syncthreads();

            // ---- phase 5: exact eval of candidates (r from smem), lex-min ----
            {
                int wc = *wcnt;
                const float* cb0 = codebooks + (size_t)stage * KCW * DIM;
                if (wc <= CAPW) {
                    for (int e = t; e < wc; e += NTHREADS) {
                        uint32_t u = wl[e];
                        int iti = u >> 16, j = u & 0xffff;
                        float ex = exact_d2(raw + iti * RSW, cb0 + (size_t)j * DIM,
                                            rrs[iti], cc_s[j]);
                        unsigned long long key = ((unsigned long long)ford(ex) << 32) | (uint32_t)j;
                        atomicMin(&ekey[iti], key);
                    }
                } else if (t < TM) {
                    float rr = rrs[t];
                    const float* rrow = raw + t * RSW;
                    float bv = 3.0e38f; int bi = KCW;
                    #pragma unroll 1
                    for (int j = 0; j < KCW; j++) {
                        float ex = exact_d2(rrow, cb0 + (size_t)j * DIM, rr, cc_s[j]);
                        if (ex < bv || (ex == bv && j < bi)) { bv = ex; bi = j; }
                    }
                    ekey[t] = ((unsigned long long)ford(bv) << 32) | (uint32_t)bi;
                }
            }
            __syncthreads();

            if (t < TM) {
                int bi = (int)(ekey[t] & 0xffffffffu);
                best[t] = bi;
                int gi = tl * TM + t;
                if (stage < 2) g_idx[stage * N_ITEMS + gi] = bi;
                if (mode == 0)      out[(size_t)gi * 3 + stage] = (float)bi;
                else if (mode == 2) ((int*)out)[(size_t)gi * 3 + stage] = bi;
            }
            __syncthreads();

            // ---- phase 6: residual update / quantize (r from smem) ----
            {
                int i = t >> 2, off = (t & 3) * 32;
                int gi = tl * TM + i;
                if (stage < 2) {
                    int bi = best[i];
                    const float4* cr = (const float4*)(codebooks + ((size_t)stage * KCW + bi) * DIM + off);
                    const float4* rg = (const float4*)(raw + i * RSW + off);
                    float4* go = (float4*)(g_res + (size_t)gi * DIM + off);
                    #pragma unroll
                    for (int m = 0; m < 8; m++) {
                        float4 r = rg[m], c = cr[m], o;
                        o.x = __fsub_rn(r.x, c.x); o.y = __fsub_rn(r.y, c.y);
                        o.z = __fsub_rn(r.z, c.z); o.w = __fsub_rn(r.w, c.w);
                        go[m] = o;
                    }
                } else if (mode != 2) {
                    int i0 = g_idx[gi], i1 = g_idx[N_ITEMS + gi], i2 = best[i];
                    const float4* c0 = (const float4*)(codebooks + (size_t)i0 * DIM + off);
                    const float4* c1 = (const float4*)(codebooks + ((size_t)KCW + i1) * DIM + off);
                    const float4* c2 = (const float4*)(codebooks + ((size_t)2 * KCW + i2) * DIM + off);
                    float* outq = (mode == 0) ? (out + (size_t)N_ITEMS * 3) : out;
                    float4* go = (float4*)(outq + (size_t)gi * DIM + off);
                    #pragma unroll
                    for (int m = 0; m < 8; m++) {
                        float4 a = c0[m], b = c1[m], c = c2[m], o;
                        o.x = __fadd_rn(__fadd_rn(a.x, b.x), c.x);
                        o.y = __fadd_rn(__fadd_rn(a.y, b.y), c.y);
                        o.z = __fadd_rn(__fadd_rn(a.z, b.z), c.z);
                        o.w = __fadd_rn(__fadd_rn(a.w, b.w), c.w);
                        go[m] = o;
                    }
                }
            }
        }
    }
}

extern "C" void kernel_launch(void* const* d_in, const int* in_sizes, int n_in,
                              void* d_out, int out_size)
{
    const float* x   = (const float*)d_in[0];
    const float* cbk = (const float*)d_in[1];
    if (n_in >= 2 && in_sizes[0] == NCB * KCW * DIM && in_sizes[1] == N_ITEMS * DIM) {
        const float* tmp = x; x = cbk; cbk = tmp;
    }
    int mode;
    if (out_size == N_ITEMS * (3 + DIM))      mode = 0;
    else if (out_size == N_ITEMS * DIM)       mode = 1;
    else if (out_size == N_ITEMS * 3)         mode = 2;
    else                                       mode = (out_size > N_ITEMS * DIM) ? 0 : 1;

    cc_kernel<<<(NCB * KCW + 31) / 32, 32>>>(cbk);
    cudaFuncSetAttribute(rvq_kernel, cudaFuncAttributeMaxDynamicSharedMemorySize, SMEM_BYTES);
    rvq_kernel<<<GRID, NTHREADS, SMEM_BYTES>>>(x, cbk, (float*)d_out, mode);
}

// round 14
// speedup vs baseline: 1.2495x; 1.2495x over previous
#include <cuda_runtime.h>
#include <cuda_bf16.h>
#include <cstdint>

#define N_ITEMS  262144
#define DIM      128
#define NCB      3
#define KCW      256
#define TM       64
#define NTILES   (N_ITEMS / TM)   // 4096
#define NTHREADS 256
#define GRID     296
#define STB      272              // B row stride bytes
#define RSW      132              // raw row stride words
#define CAPW     1536
#define MCOEF    0.040f

__device__ float g_cc[NCB * KCW];
__device__ int   g_cmax[NCB];
__device__ float g_res[(size_t)N_ITEMS * DIM];
__device__ int   g_idx[2 * N_ITEMS];

__device__ __forceinline__ uint32_t s2u(const void* p) {
    return (uint32_t)__cvta_generic_to_shared(p);
}
#define CPA16(saddr, gptr) asm volatile("cp.async.ca.shared.global [%0], [%1], 16;" :: "r"(saddr), "l"(gptr))
#define CPCOMMIT()         asm volatile("cp.async.commit_group;")
#define CPWAIT0()          asm volatile("cp.async.wait_group 0;" ::: "memory")
#define LDSM4(r0,r1,r2,r3,a) asm volatile("ldmatrix.sync.aligned.m8n8.x4.shared.b16 {%0,%1,%2,%3}, [%4];" : "=r"(r0),"=r"(r1),"=r"(r2),"=r"(r3) : "r"(a))
#define MMA16816(d,a0,a1,a2,a3,b0,b1) asm volatile( \
    "mma.sync.aligned.m16n8k16.row.col.f32.bf16.bf16.f32 " \
    "{%0,%1,%2,%3}, {%4,%5,%6,%7}, {%8,%9}, {%0,%1,%2,%3};" \
    : "+f"((d)[0]),"+f"((d)[1]),"+f"((d)[2]),"+f"((d)[3]) \
    : "r"(a0),"r"(a1),"r"(a2),"r"(a3),"r"(b0),"r"(b1))
#define CVTBF2(o, lo, hi) asm("cvt.rn.bf16x2.f32 %0, %1, %2;" : "=r"(o) : "f"(hi), "f"(lo))

__device__ __forceinline__ uint32_t ford(float f) {
    uint32_t u = __float_as_uint(f);
    return (u & 0x80000000u) ? ~u : (u | 0x80000000u);
}

__global__ void cc_kernel(const float* __restrict__ codebooks) {
    int row = blockIdx.x * 32 + threadIdx.x;
    if (row >= NCB * KCW) return;
    const float* r = codebooks + (size_t)row * DIM;
    double s = 0.0;
    #pragma unroll 8
    for (int k = 0; k < DIM; k++) { double v = (double)r[k]; s += v * v; }
    g_cc[row] = (float)s;
    float nrm = sqrtf((float)s) * 1.0001f;
    atomicMax(&g_cmax[row / KCW], __float_as_int(nrm));
}

// exact d2: sequential k-ascending fmaf chain (validated R3-R13)
__device__ __noinline__ float exact_d2(const float* __restrict__ r,
                                       const float* __restrict__ c,
                                       float rr, float ccj) {
    float dot = 0.f;
    #pragma unroll
    for (int m = 0; m < 32; m++) {
        float4 a = ((const float4*)r)[m];
        float4 b = ((const float4*)c)[m];
        dot = __fmaf_rn(a.x, b.x, dot);
        dot = __fmaf_rn(a.y, b.y, dot);
        dot = __fmaf_rn(a.z, b.z, dot);
        dot = __fmaf_rn(a.w, b.w, dot);
    }
    return __fadd_rn(__fmaf_rn(-2.f, dot, rr), ccj);
}

// smem offsets (bytes, from 1024-aligned base)
#define O_B     0            // 256*272 = 69632
#define O_R0    69632        // 64*528  = 33792
#define O_CC    103424       // 1024
#define O_RRS   104448       // 256
#define O_HM    104704       // 512
#define O_EKEY  105216       // 512
#define O_WL    105728       // 1536*4 = 6144
#define O_BEST  111872       // 256
#define O_WCNT  112128       // 16
#define SMEM_BYTES (112144 + 1024)

__global__ __launch_bounds__(NTHREADS, 2)
void rvq_kernel(const float* __restrict__ x,
                const float* __restrict__ codebooks,
                float* __restrict__ out, int mode)
{
    extern __shared__ char smraw[];
    char* smem = (char*)(((uintptr_t)smraw + 1023) & ~(uintptr_t)1023);
    float* raw  = (float*)(smem + O_R0);
    float* cc_s = (float*)(smem + O_CC);
    float* rrs  = (float*)(smem + O_RRS);
    float* hm   = (float*)(smem + O_HM);      // [2][64]
    unsigned long long* ekey = (unsigned long long*)(smem + O_EKEY);
    uint32_t* wl = (uint32_t*)(smem + O_WL);
    int*   best = (int*)(smem + O_BEST);
    int*   wcnt = (int*)(smem + O_WCNT);

    const int t = threadIdx.x, w = t >> 5, lane = t & 31;
    const uint32_t sB = s2u(smem + O_B);
    const int mrow0 = 16 * (w & 3);           // warp's 16-item block (TM=64)
    const int colbase = 128 * (w >> 2);       // warp's 128-cw half

    for (int stage = 0; stage < NCB; stage++) {
        __syncthreads();
        const float cmax = __int_as_float(g_cmax[stage]);
        // ---- B conversion (hi bf16): 1 thread per codeword row ----
        {
            const float4* cr = (const float4*)(codebooks + ((size_t)stage * KCW + t) * DIM);
            char* hrow = smem + O_B + t * STB;
            #pragma unroll
            for (int m = 0; m < 16; m++) {
                float4 v0 = cr[2 * m], v1 = cr[2 * m + 1];
                uint4 o;
                CVTBF2(o.x, v0.x, v0.y); CVTBF2(o.y, v0.z, v0.w);
                CVTBF2(o.z, v1.x, v1.y); CVTBF2(o.w, v1.z, v1.w);
                *(uint4*)(hrow + m * 16) = o;
            }
            cc_s[t] = g_cc[stage * KCW + t];
        }
        const float* src = (stage == 0) ? x : g_res;
        __syncthreads();

        for (int tl = blockIdx.x; tl < NTILES; tl += GRID) {
            // ---- load raw tile via cp.async (cross-CTA overlap hides latency) ----
            {
                const char* gb = (const char*)(src + (size_t)tl * (TM * DIM));
                uint32_t sb = s2u(raw);
                #pragma unroll
                for (int n = 0; n < 8; n++) {
                    int g = t + NTHREADS * n;    // 0..2047 granules of 16B
                    CPA16(sb + (g >> 5) * (RSW * 4) + (g & 31) * 16, gb + g * 16);
                }
                CPCOMMIT();
                CPWAIT0();
            }
            __syncthreads();

            // ---- phase 1: rr (validated double chains + shfl) + init ----
            {
                int i = t >> 2, q = t & 3;
                const float4* rp = (const float4*)(raw + i * RSW + q * 32);
                double s = 0.0;
                #pragma unroll
                for (int m = 0; m < 8; m++) {
                    float4 v = rp[m];
                    double a = v.x, b = v.y, c = v.z, d = v.w;
                    s += a * a; s += b * b; s += c * c; s += d * d;
                }
                s += __shfl_xor_sync(0xffffffffu, s, 1);
                s += __shfl_xor_sync(0xffffffffu, s, 2);
                if (q == 0) rrs[i] = (float)s;
                if (t < TM) ekey[t] = ~0ull;
                if (t == 0) *wcnt = 0;
            }
            __syncthreads();

            // ---- phase 2: single-pass hi x hi MMA; A from raw (LDS + cvt) ----
            float d[16][4];
            #pragma unroll
            for (int nt = 0; nt < 16; nt++)
                #pragma unroll
                for (int e = 0; e < 4; e++) d[nt][e] = 0.f;

            const float* ar0 = raw + (mrow0 + (lane >> 2)) * RSW + (lane & 3) * 2;
            const float* ar1 = ar0 + 8 * RSW;
            const uint32_t bAddr0 = sB + (colbase + ((lane >> 4) & 1) * 8 + (lane & 7)) * STB
                                       + ((lane >> 3) & 1) * 16;
            #pragma unroll 1
            for (int ks = 0; ks < 8; ks++) {
                int k0 = ks * 16;
                float2 f0 = *(const float2*)(ar0 + k0);
                float2 f1 = *(const float2*)(ar1 + k0);
                float2 f2 = *(const float2*)(ar0 + k0 + 8);
                float2 f3 = *(const float2*)(ar1 + k0 + 8);
                uint32_t a0, a1, a2, a3;
                CVTBF2(a0, f0.x, f0.y);
                CVTBF2(a1, f1.x, f1.y);
                CVTBF2(a2, f2.x, f2.y);
                CVTBF2(a3, f3.x, f3.y);
                #pragma unroll
                for (int ntp = 0; ntp < 8; ntp++) {
                    uint32_t b0, b1, b2, b3;
                    LDSM4(b0, b1, b2, b3, bAddr0 + ntp * 16 * STB + ks * 32);
                    MMA16816(d[2 * ntp],     a0, a1, a2, a3, b0, b1);
                    MMA16816(d[2 * ntp + 1], a0, a1, a2, a3, b2, b3);
                }
            }

            // ---- phase 3: approx d2 + per-item half-min ----
            const int item0 = mrow0 + (lane >> 2);
            const int item1 = item0 + 8;
            const float rr0 = rrs[item0], rr1 = rrs[item1];
            float mn0 = 3.0e38f, mn1 = 3.0e38f;
            #pragma unroll
            for (int nt = 0; nt < 16; nt++) {
                int n = colbase + nt * 8 + 2 * (lane & 3);
                float c0 = cc_s[n], c1 = cc_s[n + 1];
                d[nt][0] = __fadd_rn(__fmaf_rn(-2.f, d[nt][0], rr0), c0);
                d[nt][1] = __fadd_rn(__fmaf_rn(-2.f, d[nt][1], rr0), c1);
                d[nt][2] = __fadd_rn(__fmaf_rn(-2.f, d[nt][2], rr1), c0);
                d[nt][3] = __fadd_rn(__fmaf_rn(-2.f, d[nt][3], rr1), c1);
                mn0 = fminf(mn0, fminf(d[nt][0], d[nt][1]));
                mn1 = fminf(mn1, fminf(d[nt][2], d[nt][3]));
            }
            mn0 = fminf(mn0, __shfl_xor_sync(0xffffffffu, mn0, 1));
            mn0 = fminf(mn0, __shfl_xor_sync(0xffffffffu, mn0, 2));
            mn1 = fminf(mn1, __shfl_xor_sync(0xffffffffu, mn1, 1));
            mn1 = fminf(mn1, __shfl_xor_sync(0xffffffffu, mn1, 2));
            if ((lane & 3) == 0) {
                hm[(w >> 2) * TM + item0] = mn0;
                hm[(w >> 2) * TM + item1] = mn1;
            }
            __syncthreads();

            // ---- phase 4: candidate collection (provable 2M window) ----
            {
                float thr0 = fminf(hm[item0], hm[TM + item0]) + MCOEF * sqrtf(rr0) * cmax + 1e-3f;
                float thr1 = fminf(hm[item1], hm[TM + item1]) + MCOEF * sqrtf(rr1) * cmax + 1e-3f;
                #pragma unroll
                for (int nt = 0; nt < 16; nt++) {
                    int n = colbase + nt * 8 + 2 * (lane & 3);
                    #pragma unroll
                    for (int e = 0; e < 4; e++) {
                        int iti = (e < 2) ? item0 : item1;
                        float thr = (e < 2) ? thr0 : thr1;
                        if (d[nt][e] <= thr) {
                            int slot = atomicAdd(wcnt, 1);
                            if (slot < CAPW)
                                wl[slot] = ((uint32_t)iti << 16) | (uint32_t)(n + (e & 1));
                        }
                    }
                }
            }
            __syncthreads();

            // ---- phase 5: exact eval of candidates (r from smem), lex-min ----
            {
                int wc = *wcnt;
                const float* cb0 = codebooks + (size_t)stage * KCW * DIM;
                if (wc <= CAPW) {
                    for (int e = t; e < wc; e += NTHREADS) {
                        uint32_t u = wl[e];
                        int iti = u >> 16, j = u & 0xffff;
                        float ex = exact_d2(raw + iti * RSW, cb0 + (size_t)j * DIM,
                                            rrs[iti], cc_s[j]);
                        unsigned long long key = ((unsigned long long)ford(ex) << 32) | (uint32_t)j;
                        atomicMin(&ekey[iti], key);
                    }
                } else if (t < TM) {          // overflow fallback: full exact scan
                    float rr = rrs[t];
                    const float* rrow = raw + t * RSW;
                    float bv = 3.0e38f; int bi = KCW;
                    #pragma unroll 1
                    for (int j = 0; j < KCW; j++) {
                        float ex = exact_d2(rrow, cb0 + (size_t)j * DIM, rr, cc_s[j]);
                        if (ex < bv || (ex == bv && j < bi)) { bv = ex; bi = j; }
                    }
                    ekey[t] = ((unsigned long long)ford(bv) << 32) | (uint32_t)bi;
                }
            }
            __syncthreads();

            if (t < TM) {
                int bi = (int)(ekey[t] & 0xffffffffu);
                best[t] = bi;
                int gi = tl * TM + t;
                if (stage < 2) g_idx[stage * N_ITEMS + gi] = bi;
                if (mode == 0)      out[(size_t)gi * 3 + stage] = (float)bi;
                else if (mode == 2) ((int*)out)[(size_t)gi * 3 + stage] = bi;
            }
            __syncthreads();

            // ---- phase 6: residual update / quantize (r from smem) ----
            {
                int i = t >> 2, off = (t & 3) * 32;
                int gi = tl * TM + i;
                if (stage < 2) {
                    int bi = best[i];
                    const float4* cr = (const float4*)(codebooks + ((size_t)stage * KCW + bi) * DIM + off);
                    const float4* rg = (const float4*)(raw + i * RSW + off);
                    float4* go = (float4*)(g_res + (size_t)gi * DIM + off);
                    #pragma unroll
                    for (int m = 0; m < 8; m++) {
                        float4 r = rg[m], c = cr[m], o;
                        o.x = __fsub_rn(r.x, c.x); o.y = __fsub_rn(r.y, c.y);
                        o.z = __fsub_rn(r.z, c.z); o.w = __fsub_rn(r.w, c.w);
                        go[m] = o;
                    }
                } else if (mode != 2) {
                    int i0 = g_idx[gi], i1 = g_idx[N_ITEMS + gi], i2 = best[i];
                    const float4* c0 = (const float4*)(codebooks + (size_t)i0 * DIM + off);
                    const float4* c1 = (const float4*)(codebooks + ((size_t)KCW + i1) * DIM + off);
                    const float4* c2 = (const float4*)(codebooks + ((size_t)2 * KCW + i2) * DIM + off);
                    float* outq = (mode == 0) ? (out + (size_t)N_ITEMS * 3) : out;
                    float4* go = (float4*)(outq + (size_t)gi * DIM + off);
                    #pragma unroll
                    for (int m = 0; m < 8; m++) {
                        float4 a = c0[m], b = c1[m], c = c2[m], o;
                        o.x = __fadd_rn(__fadd_rn(a.x, b.x), c.x);
                        o.y = __fadd_rn(__fadd_rn(a.y, b.y), c.y);
                        o.z = __fadd_rn(__fadd_rn(a.z, b.z), c.z);
                        o.w = __fadd_rn(__fadd_rn(a.w, b.w), c.w);
                        go[m] = o;
                    }
                }
            }
            __syncthreads();   // raw reusable next iteration
        }
    }
}

extern "C" void kernel_launch(void* const* d_in, const int* in_sizes, int n_in,
                              void* d_out, int out_size)
{
    const float* x   = (const float*)d_in[0];
    const float* cbk = (const float*)d_in[1];
    if (n_in >= 2 && in_sizes[0] == NCB * KCW * DIM && in_sizes[1] == N_ITEMS * DIM) {
        const float* tmp = x; x = cbk; cbk = tmp;
    }
    int mode;
    if (out_size == N_ITEMS * (3 + DIM))      mode = 0;
    else if (out_size == N_ITEMS * DIM)       mode = 1;
    else if (out_size == N_ITEMS * 3)         mode = 2;
    else                                       mode = (out_size > N_ITEMS * DIM) ? 0 : 1;

    cc_kernel<<<(NCB * KCW + 31) / 32, 32>>>(cbk);
    cudaFuncSetAttribute(rvq_kernel, cudaFuncAttributeMaxDynamicSharedMemorySize, SMEM_BYTES);
    rvq_kernel<<<GRID, NTHREADS, SMEM_BYTES>>>(x, cbk, (float*)d_out, mode);
}

// round 15
// speedup vs baseline: 1.3034x; 1.0431x over previous
#include <cuda_runtime.h>
#include <cuda_bf16.h>
#include <cstdint>

#define N_ITEMS  262144
#define DIM      128
#define NCB      3
#define KCW      256
#define TM       64
#define NTILES   (N_ITEMS / TM)   // 4096
#define NTHREADS 256
#define GRID     296
#define RSW      132              // raw row stride words
#define CAPW     1536
#define MCOEF    0.040f

__device__ float g_cc[NCB * KCW];
__device__ int   g_cmax[NCB];
__device__ uint4 g_bfrag[NCB * 2 * 8 * 8 * 32];   // [stage][cb][ntp][ks][lane]

__device__ __forceinline__ uint32_t s2u(const void* p) {
    return (uint32_t)__cvta_generic_to_shared(p);
}
#define CPA16(saddr, gptr) asm volatile("cp.async.ca.shared.global [%0], [%1], 16;" :: "r"(saddr), "l"(gptr))
#define CPCOMMIT()         asm volatile("cp.async.commit_group;")
#define CPWAIT0()          asm volatile("cp.async.wait_group 0;" ::: "memory")
#define CPWAIT1()          asm volatile("cp.async.wait_group 1;" ::: "memory")
#define MMA16816(d,a0,a1,a2,a3,b0,b1) asm volatile( \
    "mma.sync.aligned.m16n8k16.row.col.f32.bf16.bf16.f32 " \
    "{%0,%1,%2,%3}, {%4,%5,%6,%7}, {%8,%9}, {%0,%1,%2,%3};" \
    : "+f"((d)[0]),"+f"((d)[1]),"+f"((d)[2]),"+f"((d)[3]) \
    : "r"(a0),"r"(a1),"r"(a2),"r"(a3),"r"(b0),"r"(b1))
#define CVTBF2(o, lo, hi) asm("cvt.rn.bf16x2.f32 %0, %1, %2;" : "=r"(o) : "f"(hi), "f"(lo))

__device__ __forceinline__ uint32_t ford(float f) {
    uint32_t u = __float_as_uint(f);
    return (u & 0x80000000u) ? ~u : (u | 0x80000000u);
}

__global__ void cc_kernel(const float* __restrict__ codebooks) {
    int row = blockIdx.x * 32 + threadIdx.x;
    if (row >= NCB * KCW) return;
    const float* r = codebooks + (size_t)row * DIM;
    double s = 0.0;
    #pragma unroll 8
    for (int k = 0; k < DIM; k++) { double v = (double)r[k]; s += v * v; }
    g_cc[row] = (float)s;
    float nrm = sqrtf((float)s) * 1.0001f;
    atomicMax(&g_cmax[row / KCW], __float_as_int(nrm));
}

// pre-pack B fragments: exactly the uint4 each lane's ldmatrix.x4 yielded in R14
__global__ void bfrag_kernel(const float* __restrict__ codebooks) {
    int idx = blockIdx.x * 256 + threadIdx.x;         // 0..12287
    if (idx >= NCB * 2 * 8 * 8 * 32) return;
    int lane = idx & 31, ks = (idx >> 5) & 7, ntp = (idx >> 8) & 7;
    int cb = (idx >> 11) & 1, stage = idx >> 12;
    int n0 = cb * 128 + ntp * 16 + (lane >> 2);
    int kb = ks * 16 + (lane & 3) * 2;
    const float* B = codebooks + (size_t)stage * KCW * DIM;
    auto pk = [&](int row, int col) {
        uint32_t lo = (uint32_t)__bfloat16_as_ushort(__float2bfloat16(B[(size_t)row * DIM + col]));
        uint32_t hi = (uint32_t)__bfloat16_as_ushort(__float2bfloat16(B[(size_t)row * DIM + col + 1]));
        return lo | (hi << 16);
    };
    uint4 o;
    o.x = pk(n0,     kb);
    o.y = pk(n0,     kb + 8);
    o.z = pk(n0 + 8, kb);
    o.w = pk(n0 + 8, kb + 8);
    g_bfrag[idx] = o;
}

// exact d2: sequential k-ascending fmaf chain (validated R3-R14)
__device__ __noinline__ float exact_d2(const float* __restrict__ r,
                                       const float* __restrict__ c,
                                       float rr, float ccj) {
    float dot = 0.f;
    #pragma unroll
    for (int m = 0; m < 32; m++) {
        float4 a = ((const float4*)r)[m];
        float4 b = ((const float4*)c)[m];
        dot = __fmaf_rn(a.x, b.x, dot);
        dot = __fmaf_rn(a.y, b.y, dot);
        dot = __fmaf_rn(a.z, b.z, dot);
        dot = __fmaf_rn(a.w, b.w, dot);
    }
    return __fadd_rn(__fmaf_rn(-2.f, dot, rr), ccj);
}

// smem offsets (bytes, from 1024-aligned base)
#define O_R0    0            // 64*528 = 33792
#define O_R1    33792        // 33792
#define O_CC    67584        // 3*1024 = 3072
#define O_RRS   70656        // 256
#define O_HM    70912        // 512
#define O_EKEY  71424        // 512
#define O_WL    71936        // 6144
#define O_BEST  78080        // 3*256 = 768
#define O_WCNT  78848        // 16
#define SMEM_BYTES (78864 + 1024)

__global__ __launch_bounds__(NTHREADS, 2)
void rvq_kernel(const float* __restrict__ x,
                const float* __restrict__ codebooks,
                float* __restrict__ out, int mode)
{
    extern __shared__ char smraw[];
    char* smem = (char*)(((uintptr_t)smraw + 1023) & ~(uintptr_t)1023);
    float* rawb[2] = { (float*)(smem + O_R0), (float*)(smem + O_R1) };
    float* cc_s = (float*)(smem + O_CC);      // [3][256]
    float* rrs  = (float*)(smem + O_RRS);
    float* hm   = (float*)(smem + O_HM);      // [2][64]
    unsigned long long* ekey = (unsigned long long*)(smem + O_EKEY);
    uint32_t* wl = (uint32_t*)(smem + O_WL);
    int*   best = (int*)(smem + O_BEST);      // [3][64]
    int*   wcnt = (int*)(smem + O_WCNT);

    const int t = threadIdx.x, w = t >> 5, lane = t & 31;
    const int mrow0 = 16 * (w & 3);           // warp's 16-item block
    const int cb    = w >> 2;                 // warp's 128-cw half
    const int colbase = 128 * cb;

    // load cc (all 3 stages) + cmax once
    {
        cc_s[t] = g_cc[t];
        cc_s[256 + t] = g_cc[256 + t];
        cc_s[512 + t] = g_cc[512 + t];
    }
    float cmax3[3];
    #pragma unroll
    for (int s = 0; s < 3; s++) cmax3[s] = __int_as_float(g_cmax[s]);

    auto prefetch_tile = [&](int tl, int buf) {
        const char* gb = (const char*)(x + (size_t)tl * (TM * DIM));
        uint32_t sb = s2u(rawb[buf]);
        #pragma unroll
        for (int n = 0; n < 8; n++) {
            int g = t + NTHREADS * n;        // 0..2047 granules of 16B
            CPA16(sb + (g >> 5) * (RSW * 4) + (g & 31) * 16, gb + g * 16);
        }
        CPCOMMIT();
    };

    int tl0 = blockIdx.x;
    if (tl0 < NTILES) prefetch_tile(tl0, 0);

    int it = 0;
    for (int tl = tl0; tl < NTILES; tl += GRID, it++) {
        int buf = it & 1;
        float* raw = rawb[buf];

        int tln = tl + GRID;
        if (tln < NTILES) { prefetch_tile(tln, buf ^ 1); CPWAIT1(); }
        else              { CPWAIT0(); }
        __syncthreads();                  // raw(tile) ready; prev tile done

        // ---- stage-0 rr (validated chains) + init ----
        {
            int i = t >> 2, q = t & 3;
            const float4* rp = (const float4*)(raw + i * RSW + q * 32);
            double s = 0.0;
            #pragma unroll
            for (int m = 0; m < 8; m++) {
                float4 v = rp[m];
                double a = v.x, b = v.y, c = v.z, d = v.w;
                s += a * a; s += b * b; s += c * c; s += d * d;
            }
            s += __shfl_xor_sync(0xffffffffu, s, 1);
            s += __shfl_xor_sync(0xffffffffu, s, 2);
            if (q == 0) rrs[i] = (float)s;
            if (t < TM) ekey[t] = ~0ull;
            if (t == 0) *wcnt = 0;
        }
        __syncthreads();

        for (int stage = 0; stage < NCB; stage++) {
            const float* ccst = cc_s + stage * KCW;
            const float cmax = cmax3[stage];

            // ---- MMA: A from raw (LDS+cvt), B frags via LDG.128 from L2 ----
            float d[16][4];
            #pragma unroll
            for (int nt = 0; nt < 16; nt++)
                #pragma unroll
                for (int e = 0; e < 4; e++) d[nt][e] = 0.f;

            const float* ar0 = raw + (mrow0 + (lane >> 2)) * RSW + (lane & 3) * 2;
            const float* ar1 = ar0 + 8 * RSW;
            const uint4* bf = g_bfrag + (size_t)(stage * 2 + cb) * 2048 + lane;

            #pragma unroll 1
            for (int ks = 0; ks < 8; ks++) {
                uint4 bv[8];
                #pragma unroll
                for (int ntp = 0; ntp < 8; ntp++)
                    bv[ntp] = __ldg(bf + (ntp * 8 + ks) * 32);
                int k0 = ks * 16;
                float2 f0 = *(const float2*)(ar0 + k0);
                float2 f1 = *(const float2*)(ar1 + k0);
                float2 f2 = *(const float2*)(ar0 + k0 + 8);
                float2 f3 = *(const float2*)(ar1 + k0 + 8);
                uint32_t a0, a1, a2, a3;
                CVTBF2(a0, f0.x, f0.y);
                CVTBF2(a1, f1.x, f1.y);
                CVTBF2(a2, f2.x, f2.y);
                CVTBF2(a3, f3.x, f3.y);
                #pragma unroll
                for (int ntp = 0; ntp < 8; ntp++) {
                    MMA16816(d[2 * ntp],     a0, a1, a2, a3, bv[ntp].x, bv[ntp].y);
                    MMA16816(d[2 * ntp + 1], a0, a1, a2, a3, bv[ntp].z, bv[ntp].w);
                }
            }

            // ---- approx d2 + per-item half-min ----
            const int item0 = mrow0 + (lane >> 2);
            const int item1 = item0 + 8;
            const float rr0 = rrs[item0], rr1 = rrs[item1];
            float mn0 = 3.0e38f, mn1 = 3.0e38f;
            #pragma unroll
            for (int nt = 0; nt < 16; nt++) {
                int n = colbase + nt * 8 + 2 * (lane & 3);
                float c0 = ccst[n], c1 = ccst[n + 1];
                d[nt][0] = __fadd_rn(__fmaf_rn(-2.f, d[nt][0], rr0), c0);
                d[nt][1] = __fadd_rn(__fmaf_rn(-2.f, d[nt][1], rr0), c1);
                d[nt][2] = __fadd_rn(__fmaf_rn(-2.f, d[nt][2], rr1), c0);
                d[nt][3] = __fadd_rn(__fmaf_rn(-2.f, d[nt][3], rr1), c1);
                mn0 = fminf(mn0, fminf(d[nt][0], d[nt][1]));
                mn1 = fminf(mn1, fminf(d[nt][2], d[nt][3]));
            }
            mn0 = fminf(mn0, __shfl_xor_sync(0xffffffffu, mn0, 1));
            mn0 = fminf(mn0, __shfl_xor_sync(0xffffffffu, mn0, 2));
            mn1 = fminf(mn1, __shfl_xor_sync(0xffffffffu, mn1, 1));
            mn1 = fminf(mn1, __shfl_xor_sync(0xffffffffu, mn1, 2));
            if ((lane & 3) == 0) {
                hm[cb * TM + item0] = mn0;
                hm[cb * TM + item1] = mn1;
            }
            __syncthreads();

            // ---- candidate collection (provable 2M window) ----
            {
                float thr0 = fminf(hm[item0], hm[TM + item0]) + MCOEF * sqrtf(rr0) * cmax + 1e-3f;
                float thr1 = fminf(hm[item1], hm[TM + item1]) + MCOEF * sqrtf(rr1) * cmax + 1e-3f;
                #pragma unroll
                for (int nt = 0; nt < 16; nt++) {
                    int n = colbase + nt * 8 + 2 * (lane & 3);
                    #pragma unroll
                    for (int e = 0; e < 4; e++) {
                        int iti = (e < 2) ? item0 : item1;
                        float thr = (e < 2) ? thr0 : thr1;
                        if (d[nt][e] <= thr) {
                            int slot = atomicAdd(wcnt, 1);
                            if (slot < CAPW)
                                wl[slot] = ((uint32_t)iti << 16) | (uint32_t)(n + (e & 1));
                        }
                    }
                }
            }
            __syncthreads();

            // ---- exact eval of candidates (r from smem), lex-min ----
            {
                int wc = *wcnt;
                const float* cb0 = codebooks + (size_t)stage * KCW * DIM;
                if (wc <= CAPW) {
                    for (int e = t; e < wc; e += NTHREADS) {
                        uint32_t u = wl[e];
                        int iti = u >> 16, j = u & 0xffff;
                        float ex = exact_d2(raw + iti * RSW, cb0 + (size_t)j * DIM,
                                            rrs[iti], ccst[j]);
                        unsigned long long key = ((unsigned long long)ford(ex) << 32) | (uint32_t)j;
                        atomicMin(&ekey[iti], key);
                    }
                } else if (t < TM) {          // overflow fallback: full exact scan
                    float rr = rrs[t];
                    const float* rrow = raw + t * RSW;
                    float bv = 3.0e38f; int bi = KCW;
                    #pragma unroll 1
                    for (int j = 0; j < KCW; j++) {
                        float ex = exact_d2(rrow, cb0 + (size_t)j * DIM, rr, ccst[j]);
                        if (ex < bv || (ex == bv && j < bi)) { bv = ex; bi = j; }
                    }
                    ekey[t] = ((unsigned long long)ford(bv) << 32) | (uint32_t)bi;
                }
            }
            __syncthreads();

            if (t < TM) {
                int bi = (int)(ekey[t] & 0xffffffffu);
                best[stage * TM + t] = bi;
                int gi = tl * TM + t;
                if (mode == 0)      out[(size_t)gi * 3 + stage] = (float)bi;
                else if (mode == 2) ((int*)out)[(size_t)gi * 3 + stage] = bi;
            }
            __syncthreads();

            // ---- update raw in place + fused rr for next stage ----
            if (stage < 2) {
                int i = t >> 2, q = t & 3, off = q * 32;
                int bi = best[stage * TM + i];
                const float4* cr = (const float4*)(codebooks + ((size_t)stage * KCW + bi) * DIM + off);
                float4* rg = (float4*)(raw + i * RSW + off);
                double s = 0.0;
                #pragma unroll
                for (int m = 0; m < 8; m++) {
                    float4 r = rg[m], c = cr[m], o;
                    o.x = __fsub_rn(r.x, c.x); o.y = __fsub_rn(r.y, c.y);
                    o.z = __fsub_rn(r.z, c.z); o.w = __fsub_rn(r.w, c.w);
                    rg[m] = o;
                    double a = o.x, b2 = o.y, c2 = o.z, d2 = o.w;
                    s += a * a; s += b2 * b2; s += c2 * c2; s += d2 * d2;
                }
                s += __shfl_xor_sync(0xffffffffu, s, 1);
                s += __shfl_xor_sync(0xffffffffu, s, 2);
                if (q == 0) rrs[i] = (float)s;
                if (t < TM) ekey[t] = ~0ull;
                if (t == 0) *wcnt = 0;
                __syncthreads();
            } else if (mode != 2) {
                // ---- quantized = fl(fl(c0 + c1) + c2), reference order ----
                int i = t >> 2, off = (t & 3) * 32;
                int gi = tl * TM + i;
                int i0 = best[0 * TM + i], i1 = best[1 * TM + i], i2 = best[2 * TM + i];
                const float4* c0 = (const float4*)(codebooks + (size_t)i0 * DIM + off);
                const float4* c1 = (const float4*)(codebooks + ((size_t)KCW + i1) * DIM + off);
                const float4* c2 = (const float4*)(codebooks + ((size_t)2 * KCW + i2) * DIM + off);
                float* outq = (mode == 0) ? (out + (size_t)N_ITEMS * 3) : out;
                float4* go = (float4*)(outq + (size_t)gi * DIM + off);
                #pragma unroll
                for (int m = 0; m < 8; m++) {
                    float4 a = c0[m], b = c1[m], c = c2[m], o;
                    o.x = __fadd_rn(__fadd_rn(a.x, b.x), c.x);
                    o.y = __fadd_rn(__fadd_rn(a.y, b.y), c.y);
                    o.z = __fadd_rn(__fadd_rn(a.z, b.z), c.z);
                    o.w = __fadd_rn(__fadd_rn(a.w, b.w), c.w);
                    go[m] = o;
                }
            }
        }
    }
}

extern "C" void kernel_launch(void* const* d_in, const int* in_sizes, int n_in,
                              void* d_out, int out_size)
{
    const float* x   = (const float*)d_in[0];
    const float* cbk = (const float*)d_in[1];
    if (n_in >= 2 && in_sizes[0] == NCB * KCW * DIM && in_sizes[1] == N_ITEMS * DIM) {
        const float* tmp = x; x = cbk; cbk = tmp;
    }
    int mode;
    if (out_size == N_ITEMS * (3 + DIM))      mode = 0;
    else if (out_size == N_ITEMS * DIM)       mode = 1;
    else if (out_size == N_ITEMS * 3)         mode = 2;
    else                                       mode = (out_size > N_ITEMS * DIM) ? 0 : 1;

    cc_kernel<<<(NCB * KCW + 31) / 32, 32>>>(cbk);
    bfrag_kernel<<<48, 256>>>(cbk);
    cudaFuncSetAttribute(rvq_kernel, cudaFuncAttributeMaxDynamicSharedMemorySize, SMEM_BYTES);
    rvq_kernel<<<GRID, NTHREADS, SMEM_BYTES>>>(x, cbk, (float*)d_out, mode);
}

// round 16
// speedup vs baseline: 1.7029x; 1.3065x over previous
#include <cuda_runtime.h>
#include <cuda_bf16.h>
#include <cstdint>

#define N_ITEMS  262144
#define DIM      128
#define NCB      3
#define KCW      256
#define TM       16               // items per pair-tile
#define NTILES   (N_ITEMS / TM)   // 16384
#define NTHREADS 256
#define GRID     296
#define NPAIR    (GRID * 4)       // 1184
#define RSW      132
#define CAPP     256
#define MCOEF    0.040f

__device__ float g_cc[NCB * KCW];
__device__ int   g_cmax[NCB];
__device__ uint4 g_bfrag[NCB * 2 * 8 * 8 * 32];   // [stage][half][ntp][ks][lane]

__device__ __forceinline__ uint32_t s2u(const void* p) {
    return (uint32_t)__cvta_generic_to_shared(p);
}
#define CPA16(saddr, gptr) asm volatile("cp.async.ca.shared.global [%0], [%1], 16;" :: "r"(saddr), "l"(gptr))
#define CPCOMMIT()         asm volatile("cp.async.commit_group;")
#define CPWAIT0()          asm volatile("cp.async.wait_group 0;" ::: "memory")
#define CPWAIT1()          asm volatile("cp.async.wait_group 1;" ::: "memory")
#define PBAR(id)           asm volatile("bar.sync %0, 64;" :: "r"(id) : "memory")
#define MMA16816(d,a0,a1,a2,a3,b0,b1) asm volatile( \
    "mma.sync.aligned.m16n8k16.row.col.f32.bf16.bf16.f32 " \
    "{%0,%1,%2,%3}, {%4,%5,%6,%7}, {%8,%9}, {%0,%1,%2,%3};" \
    : "+f"((d)[0]),"+f"((d)[1]),"+f"((d)[2]),"+f"((d)[3]) \
    : "r"(a0),"r"(a1),"r"(a2),"r"(a3),"r"(b0),"r"(b1))
#define CVTBF2(o, lo, hi) asm("cvt.rn.bf16x2.f32 %0, %1, %2;" : "=r"(o) : "f"(hi), "f"(lo))

__device__ __forceinline__ uint32_t ford(float f) {
    uint32_t u = __float_as_uint(f);
    return (u & 0x80000000u) ? ~u : (u | 0x80000000u);
}

__global__ void cc_kernel(const float* __restrict__ codebooks) {
    int row = blockIdx.x * 32 + threadIdx.x;
    if (row >= NCB * KCW) return;
    const float* r = codebooks + (size_t)row * DIM;
    double s = 0.0;
    #pragma unroll 8
    for (int k = 0; k < DIM; k++) { double v = (double)r[k]; s += v * v; }
    g_cc[row] = (float)s;
    float nrm = sqrtf((float)s) * 1.0001f;
    atomicMax(&g_cmax[row / KCW], __float_as_int(nrm));
}

__global__ void bfrag_kernel(const float* __restrict__ codebooks) {
    int idx = blockIdx.x * 256 + threadIdx.x;         // 0..12287
    if (idx >= NCB * 2 * 8 * 8 * 32) return;
    int lane = idx & 31, ks = (idx >> 5) & 7, ntp = (idx >> 8) & 7;
    int cb = (idx >> 11) & 1, stage = idx >> 12;
    int n0 = cb * 128 + ntp * 16 + (lane >> 2);
    int kb = ks * 16 + (lane & 3) * 2;
    const float* B = codebooks + (size_t)stage * KCW * DIM;
    auto pk = [&](int row, int col) {
        uint32_t lo = (uint32_t)__bfloat16_as_ushort(__float2bfloat16(B[(size_t)row * DIM + col]));
        uint32_t hi = (uint32_t)__bfloat16_as_ushort(__float2bfloat16(B[(size_t)row * DIM + col + 1]));
        return lo | (hi << 16);
    };
    uint4 o;
    o.x = pk(n0,     kb);
    o.y = pk(n0,     kb + 8);
    o.z = pk(n0 + 8, kb);
    o.w = pk(n0 + 8, kb + 8);
    g_bfrag[idx] = o;
}

// exact d2: sequential k-ascending fmaf chain (validated R3-R15)
__device__ __noinline__ float exact_d2(const float* __restrict__ r,
                                       const float* __restrict__ c,
                                       float rr, float ccj) {
    float dot = 0.f;
    #pragma unroll
    for (int m = 0; m < 32; m++) {
        float4 a = ((const float4*)r)[m];
        float4 b = ((const float4*)c)[m];
        dot = __fmaf_rn(a.x, b.x, dot);
        dot = __fmaf_rn(a.y, b.y, dot);
        dot = __fmaf_rn(a.z, b.z, dot);
        dot = __fmaf_rn(a.w, b.w, dot);
    }
    return __fadd_rn(__fmaf_rn(-2.f, dot, rr), ccj);
}

// per-pair smem block layout (bytes within pair block)
#define PO_R0    0        // 16*528 = 8448
#define PO_R1    8448     // 8448
#define PO_RRS   16896    // 64
#define PO_HM    16960    // 128
#define PO_EKEY  17088    // 128
#define PO_BEST  17216    // 192
#define PO_WL    17408    // 1024
#define PO_WCNT  18432    // 16
#define PP       18560    // pair stride
#define O_CC     (4 * PP) // 74240; cc 3072
#define SMEM_BYTES (O_CC + 3072 + 1024)

__global__ __launch_bounds__(NTHREADS, 2)
void rvq_kernel(const float* __restrict__ x,
                const float* __restrict__ codebooks,
                float* __restrict__ out, int mode)
{
    extern __shared__ char smraw[];
    char* smem = (char*)(((uintptr_t)smraw + 1023) & ~(uintptr_t)1023);
    float* cc_s = (float*)(smem + O_CC);      // [3][256]

    const int t = threadIdx.x;
    const int pair = t >> 6;                  // 0..3
    const int tp   = t & 63;                  // thread in pair
    const int wp   = (t >> 5) & 1;            // warp in pair (cw half)
    const int lane = t & 31;
    const int barid = pair + 1;

    char* pb = smem + pair * PP;
    float* rawb[2] = { (float*)(pb + PO_R0), (float*)(pb + PO_R1) };
    float* rrs  = (float*)(pb + PO_RRS);
    float* hm   = (float*)(pb + PO_HM);       // [2][16]
    unsigned long long* ekey = (unsigned long long*)(pb + PO_EKEY);
    int*   best = (int*)(pb + PO_BEST);       // [3][16]
    uint32_t* wl = (uint32_t*)(pb + PO_WL);
    int*   wcnt = (int*)(pb + PO_WCNT);

    // cc for all 3 stages, loaded once
    cc_s[t] = g_cc[t];
    cc_s[256 + t] = g_cc[256 + t];
    cc_s[512 + t] = g_cc[512 + t];
    float cmax3[3];
    #pragma unroll
    for (int s = 0; s < 3; s++) cmax3[s] = __int_as_float(g_cmax[s]);
    __syncthreads();                          // only CTA-wide sync

    const int colbase = 128 * wp;

    auto prefetch_tile = [&](int tl, int buf) {
        const char* gb = (const char*)(x + (size_t)tl * (TM * DIM));
        uint32_t sb = s2u(rawb[buf]);
        #pragma unroll
        for (int n = 0; n < 8; n++) {
            int g = tp + 64 * n;              // 0..511 granules of 16B
            CPA16(sb + (g >> 5) * (RSW * 4) + (g & 31) * 16, gb + g * 16);
        }
        CPCOMMIT();
    };

    const int P = blockIdx.x * 4 + pair;
    int tl0 = P;
    if (tl0 < NTILES) prefetch_tile(tl0, 0);

    int it = 0;
    for (int tl = tl0; tl < NTILES; tl += NPAIR, it++) {
        int buf = it & 1;
        float* raw = rawb[buf];

        int tln = tl + NPAIR;
        if (tln < NTILES) { prefetch_tile(tln, buf ^ 1); CPWAIT1(); }
        else              { CPWAIT0(); }
        PBAR(barid);                          // raw ready pair-wide

        // ---- stage-0 rr (validated chains) + init ----
        {
            int i = tp >> 2, q = tp & 3;
            const float4* rp = (const float4*)(raw + i * RSW + q * 32);
            double s = 0.0;
            #pragma unroll
            for (int m = 0; m < 8; m++) {
                float4 v = rp[m];
                double a = v.x, b = v.y, c = v.z, d = v.w;
                s += a * a; s += b * b; s += c * c; s += d * d;
            }
            s += __shfl_xor_sync(0xffffffffu, s, 1);
            s += __shfl_xor_sync(0xffffffffu, s, 2);
            if (q == 0) rrs[i] = (float)s;
            if (tp < TM) ekey[tp] = ~0ull;
            if (tp == 0) *wcnt = 0;
        }
        PBAR(barid);

        for (int stage = 0; stage < NCB; stage++) {
            const float* ccst = cc_s + stage * KCW;
            const float cmax = cmax3[stage];

            // ---- MMA: 16 items x 128 cw per warp; B frags from L2 ----
            float d[16][4];
            #pragma unroll
            for (int nt = 0; nt < 16; nt++)
                #pragma unroll
                for (int e = 0; e < 4; e++) d[nt][e] = 0.f;

            const float* ar0 = raw + (lane >> 2) * RSW + (lane & 3) * 2;
            const float* ar1 = ar0 + 8 * RSW;
            const uint4* bf = g_bfrag + (size_t)(stage * 2 + wp) * 2048 + lane;

            #pragma unroll 1
            for (int ks = 0; ks < 8; ks++) {
                uint4 bv[8];
                #pragma unroll
                for (int ntp = 0; ntp < 8; ntp++)
                    bv[ntp] = __ldg(bf + (ntp * 8 + ks) * 32);
                int k0 = ks * 16;
                float2 f0 = *(const float2*)(ar0 + k0);
                float2 f1 = *(const float2*)(ar1 + k0);
                float2 f2 = *(const float2*)(ar0 + k0 + 8);
                float2 f3 = *(const float2*)(ar1 + k0 + 8);
                uint32_t a0, a1, a2, a3;
                CVTBF2(a0, f0.x, f0.y);
                CVTBF2(a1, f1.x, f1.y);
                CVTBF2(a2, f2.x, f2.y);
                CVTBF2(a3, f3.x, f3.y);
                #pragma unroll
                for (int ntp = 0; ntp < 8; ntp++) {
                    MMA16816(d[2 * ntp],     a0, a1, a2, a3, bv[ntp].x, bv[ntp].y);
                    MMA16816(d[2 * ntp + 1], a0, a1, a2, a3, bv[ntp].z, bv[ntp].w);
                }
            }

            // ---- approx d2 + per-half min ----
            const int item0 = lane >> 2;
            const int item1 = item0 + 8;
            const float rr0 = rrs[item0], rr1 = rrs[item1];
            float mn0 = 3.0e38f, mn1 = 3.0e38f;
            #pragma unroll
            for (int nt = 0; nt < 16; nt++) {
                int n = colbase + nt * 8 + 2 * (lane & 3);
                float c0 = ccst[n], c1 = ccst[n + 1];
                d[nt][0] = __fadd_rn(__fmaf_rn(-2.f, d[nt][0], rr0), c0);
                d[nt][1] = __fadd_rn(__fmaf_rn(-2.f, d[nt][1], rr0), c1);
                d[nt][2] = __fadd_rn(__fmaf_rn(-2.f, d[nt][2], rr1), c0);
                d[nt][3] = __fadd_rn(__fmaf_rn(-2.f, d[nt][3], rr1), c1);
                mn0 = fminf(mn0, fminf(d[nt][0], d[nt][1]));
                mn1 = fminf(mn1, fminf(d[nt][2], d[nt][3]));
            }
            mn0 = fminf(mn0, __shfl_xor_sync(0xffffffffu, mn0, 1));
            mn0 = fminf(mn0, __shfl_xor_sync(0xffffffffu, mn0, 2));
            mn1 = fminf(mn1, __shfl_xor_sync(0xffffffffu, mn1, 1));
            mn1 = fminf(mn1, __shfl_xor_sync(0xffffffffu, mn1, 2));
            if ((lane & 3) == 0) {
                hm[wp * TM + item0] = mn0;
                hm[wp * TM + item1] = mn1;
            }
            PBAR(barid);

            // ---- candidate collection (provable 2M window) ----
            {
                float thr0 = fminf(hm[item0], hm[TM + item0]) + MCOEF * sqrtf(rr0) * cmax + 1e-3f;
                float thr1 = fminf(hm[item1], hm[TM + item1]) + MCOEF * sqrtf(rr1) * cmax + 1e-3f;
                #pragma unroll
                for (int nt = 0; nt < 16; nt++) {
                    int n = colbase + nt * 8 + 2 * (lane & 3);
                    #pragma unroll
                    for (int e = 0; e < 4; e++) {
                        int iti = (e < 2) ? item0 : item1;
                        float thr = (e < 2) ? thr0 : thr1;
                        if (d[nt][e] <= thr) {
                            int slot = atomicAdd(wcnt, 1);
                            if (slot < CAPP)
                                wl[slot] = ((uint32_t)iti << 16) | (uint32_t)(n + (e & 1));
                        }
                    }
                }
            }
            PBAR(barid);

            // ---- exact eval of candidates (r from smem), lex-min ----
            {
                int wc = *wcnt;
                const float* cb0 = codebooks + (size_t)stage * KCW * DIM;
                if (wc <= CAPP) {
                    for (int e = tp; e < wc; e += 64) {
                        uint32_t u = wl[e];
                        int iti = u >> 16, j = u & 0xffff;
                        float ex = exact_d2(raw + iti * RSW, cb0 + (size_t)j * DIM,
                                            rrs[iti], ccst[j]);
                        unsigned long long key = ((unsigned long long)ford(ex) << 32) | (uint32_t)j;
                        atomicMin(&ekey[iti], key);
                    }
                } else if (tp < TM) {         // overflow fallback: full exact scan
                    float rr = rrs[tp];
                    const float* rrow = raw + tp * RSW;
                    float bv = 3.0e38f; int bi = KCW;
                    #pragma unroll 1
                    for (int j = 0; j < KCW; j++) {
                        float ex = exact_d2(rrow, cb0 + (size_t)j * DIM, rr, ccst[j]);
                        if (ex < bv || (ex == bv && j < bi)) { bv = ex; bi = j; }
                    }
                    ekey[tp] = ((unsigned long long)ford(bv) << 32) | (uint32_t)bi;
                }
            }
            PBAR(barid);

            if (tp < TM) {
                int bi = (int)(ekey[tp] & 0xffffffffu);
                best[stage * TM + tp] = bi;
                int gi = tl * TM + tp;
                if (mode == 0)      out[(size_t)gi * 3 + stage] = (float)bi;
                else if (mode == 2) ((int*)out)[(size_t)gi * 3 + stage] = bi;
            }
            PBAR(barid);

            // ---- update raw in place + fused rr / final quantize ----
            if (stage < 2) {
                int i = tp >> 2, q = tp & 3, off = q * 32;
                int bi = best[stage * TM + i];
                const float4* cr = (const float4*)(codebooks + ((size_t)stage * KCW + bi) * DIM + off);
                float4* rg = (float4*)(raw + i * RSW + off);
                double s = 0.0;
                #pragma unroll
                for (int m = 0; m < 8; m++) {
                    float4 r = rg[m], c = cr[m], o;
                    o.x = __fsub_rn(r.x, c.x); o.y = __fsub_rn(r.y, c.y);
                    o.z = __fsub_rn(r.z, c.z); o.w = __fsub_rn(r.w, c.w);
                    rg[m] = o;
                    double a = o.x, b2 = o.y, c2 = o.z, d2 = o.w;
                    s += a * a; s += b2 * b2; s += c2 * c2; s += d2 * d2;
                }
                s += __shfl_xor_sync(0xffffffffu, s, 1);
                s += __shfl_xor_sync(0xffffffffu, s, 2);
                if (q == 0) rrs[i] = (float)s;
                if (tp < TM) ekey[tp] = ~0ull;
                if (tp == 0) *wcnt = 0;
                PBAR(barid);
            } else if (mode != 2) {
                int i = tp >> 2, off = (tp & 3) * 32;
                int gi = tl * TM + i;
                int i0 = best[0 * TM + i], i1 = best[1 * TM + i], i2 = best[2 * TM + i];
                const float4* c0 = (const float4*)(codebooks + (size_t)i0 * DIM + off);
                const float4* c1 = (const float4*)(codebooks + ((size_t)KCW + i1) * DIM + off);
                const float4* c2 = (const float4*)(codebooks + ((size_t)2 * KCW + i2) * DIM + off);
                float* outq = (mode == 0) ? (out + (size_t)N_ITEMS * 3) : out;
                float4* go = (float4*)(outq + (size_t)gi * DIM + off);
                #pragma unroll
                for (int m = 0; m < 8; m++) {
                    float4 a = c0[m], b = c1[m], c = c2[m], o;
                    o.x = __fadd_rn(__fadd_rn(a.x, b.x), c.x);
                    o.y = __fadd_rn(__fadd_rn(a.y, b.y), c.y);
                    o.z = __fadd_rn(__fadd_rn(a.z, b.z), c.z);
                    o.w = __fadd_rn(__fadd_rn(a.w, b.w), c.w);
                    go[m] = o;
                }
            }
        }
    }
}

extern "C" void kernel_launch(void* const* d_in, const int* in_sizes, int n_in,
                              void* d_out, int out_size)
{
    const float* x   = (const float*)d_in[0];
    const float* cbk = (const float*)d_in[1];
    if (n_in >= 2 && in_sizes[0] == NCB * KCW * DIM && in_sizes[1] == N_ITEMS * DIM) {
        const float* tmp = x; x = cbk; cbk = tmp;
    }
    int mode;
    if (out_size == N_ITEMS * (3 + DIM))      mode = 0;
    else if (out_size == N_ITEMS * DIM)       mode = 1;
    else if (out_size == N_ITEMS * 3)         mode = 2;
    else                                       mode = (out_size > N_ITEMS * DIM) ? 0 : 1;

    cc_kernel<<<(NCB * KCW + 31) / 32, 32>>>(cbk);
    bfrag_kernel<<<48, 256>>>(cbk);
    cudaFuncSetAttribute(rvq_kernel, cudaFuncAttributeMaxDynamicSharedMemorySize, SMEM_BYTES);
    rvq_kernel<<<GRID, NTHREADS, SMEM_BYTES>>>(x, cbk, (float*)d_out, mode);
}